// round 16
// baseline (speedup 1.0000x reference)
#include <cuda_runtime.h>
#include <cstdint>

// MLP [N,4]->128->128->128->2, tanh; N=524288.
// R14: R13 (fp16 single-product HMMA, register-resident A frags, group-interleaved
// epilogue, 16 warps/CTA) with HW tanh.approx.f32 (1 MUFU/tanh instead of 2).
// MUFU was the #1 pipe term (3072 cyc/tile); this halves it. Error budget:
// 3.85e-4 (fp16 quant, measured) + ~3e-4 (tanh.approx, 3 layers) < 1e-3 gate.

#define HID 128
#define NTHREADS 512
#define NWARPS 16
#define RPITCH 272u            // weight tile row pitch (bytes); conflict-free ldmatrix

// smem byte offsets
#define W2H    0u              // W^T tiles [j][k] fp16, 128 rows x 272B
#define W3H    34816u
#define SW1_O  69632u          // 512 f
#define SB1_O  71680u          // 128 f
#define SB2_O  72192u
#define SB3_O  72704u
#define SW4_O  73216u          // 256 f
#define SMEM_BYTES 74240u

typedef uint32_t u32;

__device__ __forceinline__ u32 smem_u32(const void* p) {
    u32 a;
    asm("{ .reg .u64 t; cvta.to.shared.u64 t, %1; cvt.u32.u64 %0, t; }" : "=r"(a) : "l"(p));
    return a;
}

#define LDSM4(r0, r1, r2, r3, addr) \
    asm volatile("ldmatrix.sync.aligned.m8n8.x4.shared.b16 {%0,%1,%2,%3}, [%4];" \
                 : "=r"(r0), "=r"(r1), "=r"(r2), "=r"(r3) : "r"(addr))

#define MMA16816(d, a0, a1, a2, a3, b0, b1) \
    asm volatile("mma.sync.aligned.m16n8k16.row.col.f32.f16.f16.f32 " \
                 "{%0,%1,%2,%3}, {%4,%5,%6,%7}, {%8,%9}, {%0,%1,%2,%3};" \
                 : "+f"((d)[0]), "+f"((d)[1]), "+f"((d)[2]), "+f"((d)[3]) \
                 : "r"(a0), "r"(a1), "r"(a2), "r"(a3), "r"(b0), "r"(b1))

// HW tanh (sm_75+): single MUFU op, max rel err ~2^-11.
__device__ __forceinline__ float tanh_a(float v) {
    float r;
    asm("tanh.approx.f32 %0, %1;" : "=f"(r) : "f"(v));
    return r;
}

// fp32 pair -> rn fp16x2; v0 -> low half (even column)
__device__ __forceinline__ u32 pack_f16(float v0, float v1) {
    u32 r;
    asm("cvt.rn.f16x2.f32 %0, %1, %2;" : "=r"(r) : "f"(v1), "f"(v0));
    return r;
}

// stage W[k][j] (128x128 f32, j contiguous) -> transposed fp16 tiles [j][k] (rn)
__device__ __forceinline__ void stage_weights(char* sm, u32 off,
                                              const float* __restrict__ Wg, int t) {
    for (int idx = t; idx < 64 * 128; idx += NTHREADS) {
        int j = idx & 127, k = (idx >> 7) << 1;
        float w0 = Wg[k * HID + j], w1 = Wg[(k + 1) * HID + j];
        *(u32*)(sm + off + (u32)j * RPITCH + (u32)k * 2u) = pack_f16(w0, w1);
    }
}

// 64 MMAs for one n32 group (n16 blocks 2g, 2g+1) of one layer.
__device__ __forceinline__ void group_mma(const u32 a[8][4], u32 wh, int g,
                                          float acc[4][4]) {
#pragma unroll
    for (int ks = 0; ks < 8; ++ks) {
        const u32 o0 = (u32)(2 * g)     * 4352u + (u32)ks * 32u;
        const u32 o1 = (u32)(2 * g + 1) * 4352u + (u32)ks * 32u;
        u32 h00, h01, h02, h03, h10, h11, h12, h13;
        LDSM4(h00, h01, h02, h03, wh + o0);
        LDSM4(h10, h11, h12, h13, wh + o1);
        MMA16816(acc[0], a[ks][0], a[ks][1], a[ks][2], a[ks][3], h00, h01);
        MMA16816(acc[1], a[ks][0], a[ks][1], a[ks][2], a[ks][3], h02, h03);
        MMA16816(acc[2], a[ks][0], a[ks][1], a[ks][2], a[ks][3], h10, h11);
        MMA16816(acc[3], a[ks][0], a[ks][1], a[ks][2], a[ks][3], h12, h13);
    }
}

// one hidden layer: in-frags -> out-frags, group-interleaved epilogue
__device__ __forceinline__ void layer_mid(const u32 a[8][4], u32 wh,
                                          const float* __restrict__ bias,
                                          int qc, u32 o[8][4]) {
#pragma unroll
    for (int g = 0; g < 4; ++g) {
        float acc[4][4];
#pragma unroll
        for (int q = 0; q < 4; ++q) {
            int j0 = (g * 4 + q) * 8 + qc;
            float bb0 = bias[j0], bb1 = bias[j0 + 1];
            acc[q][0] = bb0; acc[q][1] = bb1; acc[q][2] = bb0; acc[q][3] = bb1;
        }
        group_mma(a, wh, g, acc);
#pragma unroll
        for (int q = 0; q < 4; ++q) {
            int nQ = g * 4 + q;
            float v0 = tanh_a(acc[q][0]);
            float v1 = tanh_a(acc[q][1]);
            float v2 = tanh_a(acc[q][2]);
            float v3 = tanh_a(acc[q][3]);
            int ks2 = nQ >> 1, oo = (nQ & 1) * 2;
            o[ks2][oo]     = pack_f16(v0, v1);
            o[ks2][oo + 1] = pack_f16(v2, v3);
        }
    }
}

__global__ __launch_bounds__(NTHREADS, 1)
void mlp_hmma7(const float* __restrict__ X,  const float* __restrict__ Y,
               const float* __restrict__ C1, const float* __restrict__ C2,
               const float* __restrict__ W1, const float* __restrict__ b1,
               const float* __restrict__ W2, const float* __restrict__ b2,
               const float* __restrict__ W3, const float* __restrict__ b3,
               const float* __restrict__ W4, const float* __restrict__ b4,
               float* __restrict__ out, int npts) {
    extern __shared__ __align__(128) char sm[];
    const u32 smB = smem_u32(sm);
    const int t = threadIdx.x, w = t >> 5, lane = t & 31;

    float* sW1f = (float*)(sm + SW1_O);
    float* sB1f = (float*)(sm + SB1_O);
    float* sB2f = (float*)(sm + SB2_O);
    float* sB3f = (float*)(sm + SB3_O);
    float* sW4f = (float*)(sm + SW4_O);

    // ---- one-time staging ----
    for (int i = t; i < 512; i += NTHREADS) sW1f[i] = W1[i];
    if (t < 128) { sB1f[t] = b1[t]; sB2f[t] = b2[t]; sB3f[t] = b3[t]; }
    if (t < 256) sW4f[t] = W4[t];
    stage_weights(sm, W2H, W2, t);
    stage_weights(sm, W3H, W3, t);
    const float b40 = b4[0], b41 = b4[1];
    __syncthreads();

    const int qr = lane >> 2;           // fragment row within stripe
    const int qc = (lane & 3) * 2;      // fragment col pair base
    const u32 offB = (u32)(((lane & 7) + ((lane >> 4) & 1) * 8) * RPITCH
                           + ((lane >> 3) & 1) * 16);
    const u32 w2h = smB + W2H + offB;
    const u32 w3h = smB + W3H + offB;

    const int n16 = (npts + 15) >> 4;                 // 16-point micro-tiles
    const int gw  = blockIdx.x * NWARPS + w;
    const int nw  = gridDim.x * NWARPS;

    for (int wt = gw; wt < n16; wt += nw) {
        const int r0 = wt * 16 + qr, r1 = r0 + 8;
        const bool ok0 = r0 < npts, ok1 = r1 < npts;
        const float x0 = ok0 ? X[r0] : 0.f, y0 = ok0 ? Y[r0] : 0.f;
        const float p0 = ok0 ? C1[r0] : 0.f, q0 = ok0 ? C2[r0] : 0.f;
        const float x1 = ok1 ? X[r1] : 0.f, y1 = ok1 ? Y[r1] : 0.f;
        const float p1 = ok1 ? C1[r1] : 0.f, q1 = ok1 ? C2[r1] : 0.f;

        u32 fa[8][4];                   // layer-1 output frags (fp16x2)
        u32 fb[8][4];                   // layer-2 output frags

        // ---- layer 1: compute directly in A-fragment pattern ----
#pragma unroll
        for (int nt = 0; nt < 16; ++nt) {
            const int j0 = nt * 8 + qc;
            const float wa0 = sW1f[j0],           wb0 = sW1f[HID + j0];
            const float wc0 = sW1f[2 * HID + j0], wd0 = sW1f[3 * HID + j0];
            const float wa1 = sW1f[j0 + 1],           wb1 = sW1f[HID + j0 + 1];
            const float wc1 = sW1f[2 * HID + j0 + 1], wd1 = sW1f[3 * HID + j0 + 1];
            const float bb0 = sB1f[j0], bb1 = sB1f[j0 + 1];

            float v0 = fmaf(q0, wd0, fmaf(p0, wc0, fmaf(y0, wb0, fmaf(x0, wa0, bb0))));
            float v1 = fmaf(q0, wd1, fmaf(p0, wc1, fmaf(y0, wb1, fmaf(x0, wa1, bb1))));
            float v2 = fmaf(q1, wd0, fmaf(p1, wc0, fmaf(y1, wb0, fmaf(x1, wa0, bb0))));
            float v3 = fmaf(q1, wd1, fmaf(p1, wc1, fmaf(y1, wb1, fmaf(x1, wa1, bb1))));
            v0 = tanh_a(v0); v1 = tanh_a(v1); v2 = tanh_a(v2); v3 = tanh_a(v3);

            const int ks = nt >> 1, o = (nt & 1) * 2;
            fa[ks][o]     = pack_f16(v0, v1);
            fa[ks][o + 1] = pack_f16(v2, v3);
        }

        // ---- layer 2: group-interleaved HMMA + epilogue ----
        layer_mid(fa, w2h, sB2f, qc, fb);

        // ---- layer 3 + fused layer-4 dot, group-interleaved ----
        float s00 = 0.f, s01 = 0.f, s10 = 0.f, s11 = 0.f;
#pragma unroll
        for (int g = 0; g < 4; ++g) {
            float acc[4][4];
#pragma unroll
            for (int q = 0; q < 4; ++q) {
                int j0 = (g * 4 + q) * 8 + qc;
                float bb0 = sB3f[j0], bb1 = sB3f[j0 + 1];
                acc[q][0] = bb0; acc[q][1] = bb1; acc[q][2] = bb0; acc[q][3] = bb1;
            }
            group_mma(fb, w3h, g, acc);
#pragma unroll
            for (int q = 0; q < 4; ++q) {
                int j0 = (g * 4 + q) * 8 + qc;
                float h0 = tanh_a(acc[q][0]);
                float h1 = tanh_a(acc[q][1]);
                float h2 = tanh_a(acc[q][2]);
                float h3 = tanh_a(acc[q][3]);
                float2 u0 = *(const float2*)(sW4f + 2 * j0);
                float2 u1 = *(const float2*)(sW4f + 2 * j0 + 2);
                s00 = fmaf(h0, u0.x, s00); s01 = fmaf(h0, u0.y, s01);
                s00 = fmaf(h1, u1.x, s00); s01 = fmaf(h1, u1.y, s01);
                s10 = fmaf(h2, u0.x, s10); s11 = fmaf(h2, u0.y, s11);
                s10 = fmaf(h3, u1.x, s10); s11 = fmaf(h3, u1.y, s11);
            }
        }
        // reduce across the 4 lanes of each row group and store
#pragma unroll
        for (int d = 1; d <= 2; d <<= 1) {
            s00 += __shfl_xor_sync(0xFFFFFFFFu, s00, d);
            s01 += __shfl_xor_sync(0xFFFFFFFFu, s01, d);
            s10 += __shfl_xor_sync(0xFFFFFFFFu, s10, d);
            s11 += __shfl_xor_sync(0xFFFFFFFFu, s11, d);
        }
        if ((lane & 3) == 0) {
            if (ok0) *(float2*)(out + 2 * (size_t)r0) = make_float2(b40 + s00, b41 + s01);
            if (ok1) *(float2*)(out + 2 * (size_t)r1) = make_float2(b40 + s10, b41 + s11);
        }
    }
}

extern "C" void kernel_launch(void* const* d_in, const int* in_sizes, int n_in,
                              void* d_out, int out_size) {
    const float* x  = (const float*)d_in[0];
    const float* y  = (const float*)d_in[1];
    const float* c1 = (const float*)d_in[2];
    const float* c2 = (const float*)d_in[3];
    const float* W1 = (const float*)d_in[4];
    const float* b1 = (const float*)d_in[5];
    const float* W2 = (const float*)d_in[6];
    const float* b2 = (const float*)d_in[7];
    const float* W3 = (const float*)d_in[8];
    const float* b3 = (const float*)d_in[9];
    const float* W4 = (const float*)d_in[10];
    const float* b4 = (const float*)d_in[11];
    float* out = (float*)d_out;

    const int npts = in_sizes[0];

    int dev = 0, sms = 148;
    cudaGetDevice(&dev);
    cudaDeviceGetAttribute(&sms, cudaDevAttrMultiProcessorCount, dev);
    int n16 = (npts + 15) / 16;
    int maxCtas = (n16 + NWARPS - 1) / NWARPS;
    int grid = sms < maxCtas ? sms : maxCtas;

    cudaFuncSetAttribute(mlp_hmma7, cudaFuncAttributeMaxDynamicSharedMemorySize, SMEM_BYTES);
    mlp_hmma7<<<grid, NTHREADS, SMEM_BYTES>>>(x, y, c1, c2, W1, b1, W2, b2, W3, b3, W4, b4,
                                              out, npts);
}